// round 1
// baseline (speedup 1.0000x reference)
#include <cuda_runtime.h>
#include <math.h>

#define TWO_PI_F   6.283185307179586f
#define INV_TWO_PI 0.15915494309189535f
#define NT      12
#define KMIX    16
#define HDIM    256
#define LLEN    3072
#define BATCH   64
#define NSITES  1024          // LLEN / 3
#define TM      32            // sites per CTA
#define THREADS 256
#define CHUNKS  (NSITES / TM)             // 32
#define CTAS    (BATCH * CHUNKS)          // 2048
#define EPSF    1e-6f

// Scratch (no allocations allowed)
__device__ float g_z[BATCH * LLEN];
__device__ float g_part[NT * CTAS];

__device__ __forceinline__ float mod2pi(float x) {
    float r = fmodf(x, TWO_PI_F);
    return (r < 0.f) ? r + TWO_PI_F : r;
}

__global__ void init_kernel(const float* __restrict__ z_in) {
    int i = blockIdx.x * blockDim.x + threadIdx.x;
    if (i < BATCH * LLEN) g_z[i] = z_in[i];
}

__global__ __launch_bounds__(THREADS)
void step_kernel(const float* __restrict__ W1, const float* __restrict__ b1,
                 const float* __restrict__ W2, const float* __restrict__ b2,
                 const float* __restrict__ W3, const float* __restrict__ b3,
                 int t, int off)
{
    __shared__ float hbuf[TM * HDIM];     // h1 then h2 (32 KB)
    __shared__ float pbuf[TM * 48];       // params (6 KB)
    __shared__ float c1s[TM], c2s[TM], svs[TM], dsds[TM], lgs[TM], zrs[TM];

    const int tid   = threadIdx.x;
    const int b     = blockIdx.x >> 5;          // batch
    const int chunk = blockIdx.x & 31;

    const float* W1t = W1 + t * 2 * HDIM;
    const float* b1t = b1 + t * HDIM;
    const float* W2t = W2 + (size_t)t * HDIM * HDIM;
    const float* b2t = b2 + t * HDIM;
    const float* W3t = W3 + t * HDIM * 48;
    const float* b3t = b3 + t * 48;
    const float* zrow = g_z + b * LLEN;

    // -------- phase 0: per-site context ----------
    if (tid < TM) {
        int jj  = chunk * TM + tid;
        int idx = 3 * jj + off;
        int im2 = idx - 2; if (im2 < 0) im2 += LLEN;
        int im1 = idx - 1; if (im1 < 0) im1 += LLEN;
        int ip1 = idx + 1; if (ip1 >= LLEN) ip1 -= LLEN;
        int ip2 = idx + 2; if (ip2 >= LLEN) ip2 -= LLEN;
        float zm2 = zrow[im2], zm1 = zrow[im1], z0 = zrow[idx];
        float zp1 = zrow[ip1], zp2 = zrow[ip2];
        c1s[tid] = mod2pi(zm1 - zm2);
        c2s[tid] = mod2pi(zp2 - zp1);
        float Vc = mod2pi(z0 - zm1);
        float u  = fminf(fmaxf(Vc * INV_TWO_PI, EPSF), 1.f - EPSF);
        float a  = u * u;
        float bb = (1.f - u) * (1.f - u);
        float den = a + bb;
        float sv  = a / den;
        float dsdu = 2.f * u * (1.f - u) / (den * den);
        sv = fminf(fmaxf(sv, EPSF), 1.f - EPSF);
        svs[tid]  = sv;
        dsds[tid] = dsdu;
        lgs[tid]  = logf(sv) - log1pf(-sv);
        zrs[tid]  = zm1;
    }
    __syncthreads();

    // -------- layer 1: h1[s][tid] ----------
    {
        float w0 = __ldg(&W1t[tid]);
        float w1 = __ldg(&W1t[HDIM + tid]);
        float bb = __ldg(&b1t[tid]);
        #pragma unroll
        for (int s = 0; s < TM; s++) {
            hbuf[s * HDIM + tid] = tanhf(fmaf(c1s[s], w0, fmaf(c2s[s], w1, bb)));
        }
    }
    __syncthreads();

    // -------- layer 2: thread owns column tid, acc over 32 sites ----------
    float acc[TM];
    {
        float bb = __ldg(&b2t[tid]);
        #pragma unroll
        for (int s = 0; s < TM; s++) acc[s] = bb;
        for (int i = 0; i < HDIM; i += 4) {
            float w0 = __ldg(&W2t[(i + 0) * HDIM + tid]);
            float w1 = __ldg(&W2t[(i + 1) * HDIM + tid]);
            float w2 = __ldg(&W2t[(i + 2) * HDIM + tid]);
            float w3 = __ldg(&W2t[(i + 3) * HDIM + tid]);
            #pragma unroll
            for (int s = 0; s < TM; s++) {
                const float4 h = *(const float4*)&hbuf[s * HDIM + i];
                float a0 = fmaf(h.x, w0, acc[s]);
                float a1 = fmaf(h.y, w1, a0);
                float a2 = fmaf(h.z, w2, a1);
                acc[s]   = fmaf(h.w, w3, a2);
            }
        }
    }
    __syncthreads();   // everyone done READING h1 before overwrite
    #pragma unroll
    for (int s = 0; s < TM; s++) hbuf[s * HDIM + tid] = tanhf(acc[s]);
    __syncthreads();

    // -------- layer 3: 4 replicas x 64 padded cols, 8 sites each ----------
    {
        int rep = tid >> 6;          // 0..3
        int p   = tid & 63;          // 0..63 (only <48 real)
        int pc  = (p < 48) ? p : 0;  // clamp for safe loads
        float bq = (p < 48) ? __ldg(&b3t[pc]) : 0.f;
        float acc3[8];
        #pragma unroll
        for (int q = 0; q < 8; q++) acc3[q] = bq;
        for (int i = 0; i < HDIM; i += 4) {
            float w0 = __ldg(&W3t[(i + 0) * 48 + pc]);
            float w1 = __ldg(&W3t[(i + 1) * 48 + pc]);
            float w2 = __ldg(&W3t[(i + 2) * 48 + pc]);
            float w3 = __ldg(&W3t[(i + 3) * 48 + pc]);
            #pragma unroll
            for (int q = 0; q < 8; q++) {
                const float4 h = *(const float4*)&hbuf[(rep * 8 + q) * HDIM + i];
                acc3[q] = fmaf(h.x, w0, fmaf(h.y, w1, fmaf(h.z, w2, fmaf(h.w, w3, acc3[q]))));
            }
        }
        if (p < 48) {
            #pragma unroll
            for (int q = 0; q < 8; q++) pbuf[(rep * 8 + q) * 48 + p] = acc3[q];
        }
    }
    __syncthreads();

    // -------- epilogue: mixture transform, one thread per site ----------
    float ldj = 0.f;
    if (tid < TM) {
        const int s = tid;
        const float* pr = &pbuf[s * 48];
        float lgt = lgs[s], sv = svs[s];
        float m = -1e30f;
        #pragma unroll
        for (int k = 0; k < KMIX; k++) m = fmaxf(m, pr[32 + k]);
        float es[KMIX]; float se = 0.f;
        #pragma unroll
        for (int k = 0; k < KMIX; k++) { es[k] = expf(pr[32 + k] - m); se += es[k]; }
        float inv_se = 1.f / se;
        float y = 0.f, dsum = 0.f;
        #pragma unroll
        for (int k = 0; k < KMIX; k++) {
            float wgt   = fmaf(es[k] * inv_se, 0.84f, 0.01f);
            float alpha = expf(pr[k]);
            float x     = alpha * (lgt + pr[16 + k]);
            float g     = 1.f / (1.f + expf(-x));
            y    = fmaf(wgt, g, y);
            dsum = fmaf(wgt * alpha, g * (1.f - g), dsum);
        }
        float dy_du = dsum / (sv * (1.f - sv)) * dsds[s];
        ldj = logf(dy_du);
        int jj  = chunk * TM + s;
        int idx = 3 * jj + off;
        g_z[b * LLEN + idx] = mod2pi(fmaf(TWO_PI_F, y, zrs[s]));
    }
    // deterministic warp reduce (tid<32 == warp 0)
    if (tid < 32) {
        #pragma unroll
        for (int o = 16; o; o >>= 1) ldj += __shfl_down_sync(0xffffffff, ldj, o);
        if (tid == 0) g_part[t * CTAS + blockIdx.x] = ldj;
    }
}

__global__ void final_kernel(float* __restrict__ out, int out_size) {
    int i = blockIdx.x * blockDim.x + threadIdx.x;
    if (i < BATCH * LLEN && i < out_size) out[i] = g_z[i];
    if (blockIdx.x == 0 && threadIdx.x < BATCH) {
        int o = BATCH * LLEN + threadIdx.x;
        if (o < out_size) {
            float s = 0.f;
            for (int t = 0; t < NT; t++)
                for (int c = 0; c < CHUNKS; c++)
                    s += g_part[t * CTAS + threadIdx.x * CHUNKS + c];
            out[o] = s;
        }
    }
}

extern "C" void kernel_launch(void* const* d_in, const int* in_sizes, int n_in,
                              void* d_out, int out_size) {
    const float* z  = (const float*)d_in[0];
    const float* W1 = (const float*)d_in[1];
    const float* b1 = (const float*)d_in[2];
    const float* W2 = (const float*)d_in[3];
    const float* b2 = (const float*)d_in[4];
    const float* W3 = (const float*)d_in[5];
    const float* b3 = (const float*)d_in[6];
    float* out = (float*)d_out;

    init_kernel<<<(BATCH * LLEN + 255) / 256, 256>>>(z);
    for (int t = 0; t < NT; t++) {
        const int off_tab[3] = {0, 2, 1};
        int off = off_tab[t % 3];
        step_kernel<<<CTAS, THREADS>>>(W1, b1, W2, b2, W3, b3, t, off);
    }
    final_kernel<<<(BATCH * LLEN + 255) / 256, 256>>>(out, out_size);
}

// round 2
// speedup vs baseline: 1.3444x; 1.3444x over previous
#include <cuda_runtime.h>
#include <math.h>

#define TWO_PI_F   6.283185307179586f
#define INV_TWO_PI 0.15915494309189535f
#define NT      12
#define KMIX    16
#define HDIM    256
#define LLEN    3072
#define BATCH   64
#define NSITES  1024          // LLEN / 3
#define TM      32            // sites per CTA
#define THREADS 256
#define CHUNKS  (NSITES / TM)             // 32
#define CTAS    (BATCH * CHUNKS)          // 2048
#define EPSF    1e-6f

// Scratch (no allocations allowed)
__device__ float g_z[BATCH * LLEN];
__device__ float g_part[NT * CTAS];

__device__ __forceinline__ float mod2pi(float x) {
    float r = fmodf(x, TWO_PI_F);
    return (r < 0.f) ? r + TWO_PI_F : r;
}

__device__ __forceinline__ float tanh_fast(float x) {
    float y;
    asm("tanh.approx.f32 %0, %1;" : "=f"(y) : "f"(x));
    return y;
}

__global__ void init_kernel(const float* __restrict__ z_in) {
    int i = blockIdx.x * blockDim.x + threadIdx.x;
    if (i < BATCH * LLEN) g_z[i] = z_in[i];
}

__global__ __launch_bounds__(THREADS)
void step_kernel(const float* __restrict__ W1, const float* __restrict__ b1,
                 const float* __restrict__ W2, const float* __restrict__ b2,
                 const float* __restrict__ W3, const float* __restrict__ b3,
                 int t, int off)
{
    __shared__ float hbuf[TM * HDIM];     // h1 then h2 (32 KB)
    __shared__ float pbuf[TM * 48];       // params (6 KB)
    __shared__ float c1s[TM], c2s[TM], svs[TM], dsds[TM], lgs[TM], zrs[TM];

    const int tid   = threadIdx.x;
    const int b     = blockIdx.x >> 5;          // batch
    const int chunk = blockIdx.x & 31;

    const float* W1t = W1 + t * 2 * HDIM;
    const float* b1t = b1 + t * HDIM;
    const float* W2t = W2 + (size_t)t * HDIM * HDIM;
    const float* b2t = b2 + t * HDIM;
    const float* W3t = W3 + t * HDIM * 48;
    const float* b3t = b3 + t * 48;
    const float* zrow = g_z + b * LLEN;

    // -------- phase 0: per-site context ----------
    if (tid < TM) {
        int jj  = chunk * TM + tid;
        int idx = 3 * jj + off;
        int im2 = idx - 2; if (im2 < 0) im2 += LLEN;
        int im1 = idx - 1; if (im1 < 0) im1 += LLEN;
        int ip1 = idx + 1; if (ip1 >= LLEN) ip1 -= LLEN;
        int ip2 = idx + 2; if (ip2 >= LLEN) ip2 -= LLEN;
        float zm2 = zrow[im2], zm1 = zrow[im1], z0 = zrow[idx];
        float zp1 = zrow[ip1], zp2 = zrow[ip2];
        c1s[tid] = mod2pi(zm1 - zm2);
        c2s[tid] = mod2pi(zp2 - zp1);
        float Vc = mod2pi(z0 - zm1);
        float u  = fminf(fmaxf(Vc * INV_TWO_PI, EPSF), 1.f - EPSF);
        float a  = u * u;
        float bb = (1.f - u) * (1.f - u);
        float den = a + bb;
        float sv  = a / den;
        float dsdu = 2.f * u * (1.f - u) / (den * den);
        sv = fminf(fmaxf(sv, EPSF), 1.f - EPSF);
        svs[tid]  = sv;
        dsds[tid] = dsdu;
        lgs[tid]  = logf(sv) - log1pf(-sv);
        zrs[tid]  = zm1;
    }
    __syncthreads();

    // -------- layer 1: h1[s][tid] ----------
    {
        float w0 = __ldg(&W1t[tid]);
        float w1 = __ldg(&W1t[HDIM + tid]);
        float bb = __ldg(&b1t[tid]);
        #pragma unroll
        for (int s = 0; s < TM; s++) {
            hbuf[s * HDIM + tid] = tanh_fast(fmaf(c1s[s], w0, fmaf(c2s[s], w1, bb)));
        }
    }
    __syncthreads();

    // -------- layer 2: 8 sites x 4 cols per thread ----------
    // cg = tid & 63 -> cols [4cg, 4cg+4);  sg = tid >> 6 -> sites [8sg, 8sg+8)
    {
        const int cg = tid & 63;
        const int sg = tid >> 6;
        const int col = 4 * cg;
        float acc[8][4];
        {
            float4 bb4 = __ldg((const float4*)&b2t[col]);
            #pragma unroll
            for (int s = 0; s < 8; s++) {
                acc[s][0] = bb4.x; acc[s][1] = bb4.y;
                acc[s][2] = bb4.z; acc[s][3] = bb4.w;
            }
        }
        const float* hrow = &hbuf[sg * 8 * HDIM];
        for (int i = 0; i < HDIM; i += 4) {
            float4 w0 = __ldg((const float4*)&W2t[(i + 0) * HDIM + col]);
            float4 w1 = __ldg((const float4*)&W2t[(i + 1) * HDIM + col]);
            float4 w2 = __ldg((const float4*)&W2t[(i + 2) * HDIM + col]);
            float4 w3 = __ldg((const float4*)&W2t[(i + 3) * HDIM + col]);
            #pragma unroll
            for (int s = 0; s < 8; s++) {
                const float4 h = *(const float4*)&hrow[s * HDIM + i];
                acc[s][0] = fmaf(h.x, w0.x, acc[s][0]);
                acc[s][1] = fmaf(h.x, w0.y, acc[s][1]);
                acc[s][2] = fmaf(h.x, w0.z, acc[s][2]);
                acc[s][3] = fmaf(h.x, w0.w, acc[s][3]);
                acc[s][0] = fmaf(h.y, w1.x, acc[s][0]);
                acc[s][1] = fmaf(h.y, w1.y, acc[s][1]);
                acc[s][2] = fmaf(h.y, w1.z, acc[s][2]);
                acc[s][3] = fmaf(h.y, w1.w, acc[s][3]);
                acc[s][0] = fmaf(h.z, w2.x, acc[s][0]);
                acc[s][1] = fmaf(h.z, w2.y, acc[s][1]);
                acc[s][2] = fmaf(h.z, w2.z, acc[s][2]);
                acc[s][3] = fmaf(h.z, w2.w, acc[s][3]);
                acc[s][0] = fmaf(h.w, w3.x, acc[s][0]);
                acc[s][1] = fmaf(h.w, w3.y, acc[s][1]);
                acc[s][2] = fmaf(h.w, w3.z, acc[s][2]);
                acc[s][3] = fmaf(h.w, w3.w, acc[s][3]);
            }
        }
        __syncthreads();   // everyone done READING h1 before overwrite
        #pragma unroll
        for (int s = 0; s < 8; s++) {
            float4 v;
            v.x = tanh_fast(acc[s][0]);
            v.y = tanh_fast(acc[s][1]);
            v.z = tanh_fast(acc[s][2]);
            v.w = tanh_fast(acc[s][3]);
            *(float4*)&hbuf[(sg * 8 + s) * HDIM + col] = v;
        }
        __syncthreads();
    }

    // -------- layer 3: 2 sites x 4 cols per thread (48 cols padded to 64) ----
    // cg3 = tid & 15 -> cols [4cg3, 4cg3+4) (valid iff < 48); sg3 = tid >> 4 -> sites 2sg3, 2sg3+1
    {
        const int cg3 = tid & 15;
        const int sg3 = tid >> 4;
        const int col  = 4 * cg3;
        const bool valid = (col < 48);
        const int colc = valid ? col : 0;
        float acc3[2][4];
        {
            float4 bb4 = __ldg((const float4*)&b3t[colc]);
            #pragma unroll
            for (int q = 0; q < 2; q++) {
                acc3[q][0] = bb4.x; acc3[q][1] = bb4.y;
                acc3[q][2] = bb4.z; acc3[q][3] = bb4.w;
            }
        }
        const float* hrow = &hbuf[sg3 * 2 * HDIM];
        for (int i = 0; i < HDIM; i += 4) {
            float4 w0 = __ldg((const float4*)&W3t[(i + 0) * 48 + colc]);
            float4 w1 = __ldg((const float4*)&W3t[(i + 1) * 48 + colc]);
            float4 w2 = __ldg((const float4*)&W3t[(i + 2) * 48 + colc]);
            float4 w3 = __ldg((const float4*)&W3t[(i + 3) * 48 + colc]);
            #pragma unroll
            for (int q = 0; q < 2; q++) {
                const float4 h = *(const float4*)&hrow[q * HDIM + i];
                acc3[q][0] = fmaf(h.x, w0.x, acc3[q][0]);
                acc3[q][1] = fmaf(h.x, w0.y, acc3[q][1]);
                acc3[q][2] = fmaf(h.x, w0.z, acc3[q][2]);
                acc3[q][3] = fmaf(h.x, w0.w, acc3[q][3]);
                acc3[q][0] = fmaf(h.y, w1.x, acc3[q][0]);
                acc3[q][1] = fmaf(h.y, w1.y, acc3[q][1]);
                acc3[q][2] = fmaf(h.y, w1.z, acc3[q][2]);
                acc3[q][3] = fmaf(h.y, w1.w, acc3[q][3]);
                acc3[q][0] = fmaf(h.z, w2.x, acc3[q][0]);
                acc3[q][1] = fmaf(h.z, w2.y, acc3[q][1]);
                acc3[q][2] = fmaf(h.z, w2.z, acc3[q][2]);
                acc3[q][3] = fmaf(h.z, w2.w, acc3[q][3]);
                acc3[q][0] = fmaf(h.w, w3.x, acc3[q][0]);
                acc3[q][1] = fmaf(h.w, w3.y, acc3[q][1]);
                acc3[q][2] = fmaf(h.w, w3.z, acc3[q][2]);
                acc3[q][3] = fmaf(h.w, w3.w, acc3[q][3]);
            }
        }
        if (valid) {
            #pragma unroll
            for (int q = 0; q < 2; q++) {
                float4 v;
                v.x = acc3[q][0]; v.y = acc3[q][1];
                v.z = acc3[q][2]; v.w = acc3[q][3];
                *(float4*)&pbuf[(sg3 * 2 + q) * 48 + col] = v;
            }
        }
    }
    __syncthreads();

    // -------- epilogue: mixture transform, one thread per site ----------
    float ldj = 0.f;
    if (tid < TM) {
        const int s = tid;
        const float* pr = &pbuf[s * 48];
        float lgt = lgs[s], sv = svs[s];
        float m = -1e30f;
        #pragma unroll
        for (int k = 0; k < KMIX; k++) m = fmaxf(m, pr[32 + k]);
        float es[KMIX]; float se = 0.f;
        #pragma unroll
        for (int k = 0; k < KMIX; k++) { es[k] = __expf(pr[32 + k] - m); se += es[k]; }
        float inv_se = 1.f / se;
        float y = 0.f, dsum = 0.f;
        #pragma unroll
        for (int k = 0; k < KMIX; k++) {
            float wgt   = fmaf(es[k] * inv_se, 0.84f, 0.01f);
            float alpha = __expf(pr[k]);
            float x     = alpha * (lgt + pr[16 + k]);
            float g     = 1.f / (1.f + __expf(-x));
            y    = fmaf(wgt, g, y);
            dsum = fmaf(wgt * alpha, g * (1.f - g), dsum);
        }
        float dy_du = dsum / (sv * (1.f - sv)) * dsds[s];
        ldj = logf(dy_du);
        int jj  = chunk * TM + s;
        int idx = 3 * jj + off;
        g_z[b * LLEN + idx] = mod2pi(fmaf(TWO_PI_F, y, zrs[s]));
    }
    // deterministic warp reduce (tid<32 == warp 0)
    if (tid < 32) {
        #pragma unroll
        for (int o = 16; o; o >>= 1) ldj += __shfl_down_sync(0xffffffff, ldj, o);
        if (tid == 0) g_part[t * CTAS + blockIdx.x] = ldj;
    }
}

__global__ void final_kernel(float* __restrict__ out, int out_size) {
    int i = blockIdx.x * blockDim.x + threadIdx.x;
    if (i < BATCH * LLEN && i < out_size) out[i] = g_z[i];
    if (blockIdx.x == 0 && threadIdx.x < BATCH) {
        int o = BATCH * LLEN + threadIdx.x;
        if (o < out_size) {
            float s = 0.f;
            for (int t = 0; t < NT; t++)
                for (int c = 0; c < CHUNKS; c++)
                    s += g_part[t * CTAS + threadIdx.x * CHUNKS + c];
            out[o] = s;
        }
    }
}

extern "C" void kernel_launch(void* const* d_in, const int* in_sizes, int n_in,
                              void* d_out, int out_size) {
    const float* z  = (const float*)d_in[0];
    const float* W1 = (const float*)d_in[1];
    const float* b1 = (const float*)d_in[2];
    const float* W2 = (const float*)d_in[3];
    const float* b2 = (const float*)d_in[4];
    const float* W3 = (const float*)d_in[5];
    const float* b3 = (const float*)d_in[6];
    float* out = (float*)d_out;

    init_kernel<<<(BATCH * LLEN + 255) / 256, 256>>>(z);
    for (int t = 0; t < NT; t++) {
        const int off_tab[3] = {0, 2, 1};
        int off = off_tab[t % 3];
        step_kernel<<<CTAS, THREADS>>>(W1, b1, W2, b2, W3, b3, t, off);
    }
    final_kernel<<<(BATCH * LLEN + 255) / 256, 256>>>(out, out_size);
}